// round 13
// baseline (speedup 1.0000x reference)
#include <cuda_runtime.h>
#include <cstdint>

// Problem constants
#define HDIM   1024
#define DIN    256
#define DOUT   256
#define BATCH  8192
#define NLAYERS 64

// Scratch (device globals; allocation-free):
__device__ float g_act[2][HDIM * BATCH];                     // activations, m-form, [H, B]
__device__ float g_xm[DIN * BATCH];                          // 2x-1, [DIN, B]
__device__ float g_wt[(size_t)NLAYERS * HDIM * HDIM];        // W transposed: [l][k][m]
__device__ float g_et[(size_t)DIN * HDIM];                   // E transposed: [k][m]
__device__ float g_ct[(size_t)HDIM * DOUT];                  // C transposed: [k][m]

enum { MODE_EXP = 0, MODE_HID = 1, MODE_OUT = 2 };

typedef unsigned long long u64;

__device__ __forceinline__ u64 pack2(float lo, float hi) {
    u64 r;
    asm("mov.b64 %0, {%1, %2};" : "=l"(r) : "f"(lo), "f"(hi));
    return r;
}
__device__ __forceinline__ void unpack2(u64 v, float& lo, float& hi) {
    asm("mov.b64 {%0, %1}, %2;" : "=f"(lo), "=f"(hi) : "l"(v));
}
__device__ __forceinline__ u64 fma2(u64 a, u64 b, u64 c) {
    u64 d;
    asm("fma.rn.f32x2 %0, %1, %2, %3;" : "=l"(d) : "l"(a), "l"(b), "l"(c));
    return d;
}

// ---------------- pre-pass kernels ----------------
__global__ void affine_kernel(const float* __restrict__ x, float* __restrict__ xm) {
    int i = blockIdx.x * blockDim.x + threadIdx.x;
    float4 v = ((const float4*)x)[i];
    v.x = 2.0f * v.x - 1.0f; v.y = 2.0f * v.y - 1.0f;
    v.z = 2.0f * v.z - 1.0f; v.w = 2.0f * v.w - 1.0f;
    ((float4*)xm)[i] = v;
}

__global__ void transpose_kernel(const float* __restrict__ in, float* __restrict__ out,
                                 int R, int Cc) {
    __shared__ float t[32][33];
    const size_t off = (size_t)blockIdx.z * R * Cc;
    in += off; out += off;
    int c0 = blockIdx.x * 32, r0 = blockIdx.y * 32;
    int lx = threadIdx.x, ly = threadIdx.y;
    #pragma unroll
    for (int i = 0; i < 32; i += 8)
        t[ly + i][lx] = in[(size_t)(r0 + ly + i) * Cc + c0 + lx];
    __syncthreads();
    #pragma unroll
    for (int i = 0; i < 32; i += 8)
        out[(size_t)(c0 + ly + i) * R + r0 + lx] = t[lx][ly + i];
}

// ---------------- main GEMM (no smem; L1-buffered direct LDG) ----------------
// At: [K, M] transposed weights. Bm: [K, N] activations. C: [M, N].
template <int MODE>
__global__ __launch_bounds__(256, 2)
void gemm_kernel(const float* __restrict__ At, const float* __restrict__ Bm,
                 float* __restrict__ C, int M, int N, int K)
{
    constexpr int TM = 8;
    const int tid = threadIdx.x;
    const int m0 = blockIdx.y * 128;
    const int n0 = blockIdx.x * 128;
    const int tx = tid & 15;
    const int ty = tid >> 4;

    u64 acc2[TM][4];
    #pragma unroll
    for (int i = 0; i < TM; i++)
        #pragma unroll
        for (int jp = 0; jp < 4; jp++) acc2[i][jp] = 0ull;

    // moving fragment pointers
    const float* pA = At + (size_t)(m0 + ty * TM);
    const float* pB = Bm + (size_t)(n0 + tx * 8);

    float a0[TM], a1[TM];
    u64 b0[4], b1[4];

    auto loadA = [&](int k, float* a) {
        const float* p = pA + (size_t)k * M;
        *(float4*)&a[0] = *(const float4*)(p);
        *(float4*)&a[4] = *(const float4*)(p + 4);
    };
    auto loadB = [&](int k, u64* b) {
        const float* p = pB + (size_t)k * N;
        const ulonglong2 v0 = *(const ulonglong2*)(p);
        const ulonglong2 v1 = *(const ulonglong2*)(p + 4);
        b[0] = v0.x; b[1] = v0.y; b[2] = v1.x; b[3] = v1.y;
    };
    auto compute = [&](const float* a, const u64* b) {
        #pragma unroll
        for (int i = 0; i < TM; i++) {
            const u64 aa = pack2(a[i], a[i]);
            #pragma unroll
            for (int jp = 0; jp < 4; jp++)
                acc2[i][jp] = fma2(aa, b[jp], acc2[i][jp]);
        }
    };

    loadA(0, a0); loadB(0, b0);
    #pragma unroll 4
    for (int k = 0; k < K; k += 2) {
        loadA(k + 1, a1); loadB(k + 1, b1);
        compute(a0, b0);
        if (k + 2 < K) { loadA(k + 2, a0); loadB(k + 2, b0); }
        compute(a1, b1);
    }

    // ---- epilogue ----
    #pragma unroll
    for (int i = 0; i < TM; i++) {
        const int row = m0 + ty * TM + i;
        #pragma unroll
        for (int j4 = 0; j4 < 2; j4++) {
            const int col = n0 + tx * 8 + j4 * 4;
            float y[4];
            unpack2(acc2[i][j4 * 2 + 0], y[0], y[1]);
            unpack2(acc2[i][j4 * 2 + 1], y[2], y[3]);
            if (MODE == MODE_HID) {
                float4 r = *(const float4*)(Bm + (size_t)row * N + col);
                y[0] += r.x; y[1] += r.y; y[2] += r.z; y[3] += r.w;
            }
            float4 o;
            #pragma unroll
            for (int q = 0; q < 4; q++) {
                float v = fminf(fmaxf(y[q], 0.0f), 1.0f);
                if (MODE != MODE_OUT) v = 2.0f * v - 1.0f;
                ((float*)&o)[q] = v;
            }
            *(float4*)(C + (size_t)row * N + col) = o;
        }
    }
}

extern "C" void kernel_launch(void* const* d_in, const int* in_sizes, int n_in,
                              void* d_out, int out_size)
{
    const float* x           = (const float*)d_in[0]; // [DIN, BATCH]
    const float* expansion   = (const float*)d_in[1]; // [HDIM, DIN]
    const float* hidden      = (const float*)d_in[2]; // [NLAYERS, HDIM, HDIM]
    const float* compression = (const float*)d_in[3]; // [DOUT, HDIM]
    float* out = (float*)d_out;                        // [DOUT, BATCH]

    float *act0, *xm, *wt, *et, *ct;
    cudaGetSymbolAddress((void**)&act0, g_act);
    cudaGetSymbolAddress((void**)&xm, g_xm);
    cudaGetSymbolAddress((void**)&wt, g_wt);
    cudaGetSymbolAddress((void**)&et, g_et);
    cudaGetSymbolAddress((void**)&ct, g_ct);
    float* act1 = act0 + (size_t)HDIM * BATCH;

    // ---- pre-pass: affine input + transpose all weight matrices ----
    affine_kernel<<<(DIN * BATCH / 4) / 256, 256>>>(x, xm);
    transpose_kernel<<<dim3(DIN / 32, HDIM / 32, 1), dim3(32, 8)>>>(expansion, et, HDIM, DIN);
    transpose_kernel<<<dim3(HDIM / 32, HDIM / 32, NLAYERS), dim3(32, 8)>>>(hidden, wt, HDIM, HDIM);
    transpose_kernel<<<dim3(HDIM / 32, DOUT / 32, 1), dim3(32, 8)>>>(compression, ct, DOUT, HDIM);

    dim3 blk(256);

    // Expansion: m0 = 2*clip(E @ (2x-1)) - 1
    gemm_kernel<MODE_EXP><<<dim3(BATCH / 128, HDIM / 128), blk>>>(
        et, xm, act0, HDIM, BATCH, DIN);

    // 64 hidden layers: m' = 2*clip(W m + m) - 1
    float* cur = act0;
    float* nxt = act1;
    for (int l = 0; l < NLAYERS; l++) {
        gemm_kernel<MODE_HID><<<dim3(BATCH / 128, HDIM / 128), blk>>>(
            wt + (size_t)l * HDIM * HDIM, cur, nxt, HDIM, BATCH, HDIM);
        float* tmp = cur; cur = nxt; nxt = tmp;
    }

    // Compression: out = clip(Cmp @ m)
    gemm_kernel<MODE_OUT><<<dim3(BATCH / 128, DOUT / 128), blk>>>(
        ct, cur, out, DOUT, BATCH, HDIM);
}

// round 14
// speedup vs baseline: 1.6189x; 1.6189x over previous
#include <cuda_runtime.h>
#include <cstdint>

// Problem constants
#define HDIM   1024
#define DIN    256
#define DOUT   256
#define BATCH  8192
#define NLAYERS 64
#define BK     16
#define BM     128
#define BN     64

// Scratch (device globals; allocation-free):
__device__ float g_act[2][HDIM * BATCH];                     // activations, m-form, [H, B]
__device__ float g_xm[DIN * BATCH];                          // 2x-1, [DIN, B]
__device__ float g_wt[(size_t)NLAYERS * HDIM * HDIM];        // W transposed: [l][k][m]
__device__ float g_et[(size_t)DIN * HDIM];                   // E transposed: [k][m]
__device__ float g_ct[(size_t)HDIM * DOUT];                  // C transposed: [k][m]

enum { MODE_EXP = 0, MODE_HID = 1, MODE_OUT = 2 };

typedef unsigned long long u64;

__device__ __forceinline__ u64 pack2(float lo, float hi) {
    u64 r;
    asm("mov.b64 %0, {%1, %2};" : "=l"(r) : "f"(lo), "f"(hi));
    return r;
}
__device__ __forceinline__ void unpack2(u64 v, float& lo, float& hi) {
    asm("mov.b64 {%0, %1}, %2;" : "=f"(lo), "=f"(hi) : "l"(v));
}
__device__ __forceinline__ u64 fma2(u64 a, u64 b, u64 c) {
    u64 d;
    asm("fma.rn.f32x2 %0, %1, %2, %3;" : "=l"(d) : "l"(a), "l"(b), "l"(c));
    return d;
}
__device__ __forceinline__ void cp16(uint32_t dst, const float* src) {
    asm volatile("cp.async.cg.shared.global [%0], [%1], 16;" :: "r"(dst), "l"(src));
}
__device__ __forceinline__ void cp_commit() {
    asm volatile("cp.async.commit_group;");
}
template <int N>
__device__ __forceinline__ void cp_wait() {
    asm volatile("cp.async.wait_group %0;" :: "n"(N));
}

// ---------------- pre-pass kernels ----------------
__global__ void affine_kernel(const float* __restrict__ x, float* __restrict__ xm) {
    int i = blockIdx.x * blockDim.x + threadIdx.x;
    float4 v = ((const float4*)x)[i];
    v.x = 2.0f * v.x - 1.0f; v.y = 2.0f * v.y - 1.0f;
    v.z = 2.0f * v.z - 1.0f; v.w = 2.0f * v.w - 1.0f;
    ((float4*)xm)[i] = v;
}

__global__ void transpose_kernel(const float* __restrict__ in, float* __restrict__ out,
                                 int R, int Cc) {
    __shared__ float t[32][33];
    const size_t off = (size_t)blockIdx.z * R * Cc;
    in += off; out += off;
    int c0 = blockIdx.x * 32, r0 = blockIdx.y * 32;
    int lx = threadIdx.x, ly = threadIdx.y;
    #pragma unroll
    for (int i = 0; i < 32; i += 8)
        t[ly + i][lx] = in[(size_t)(r0 + ly + i) * Cc + c0 + lx];
    __syncthreads();
    #pragma unroll
    for (int i = 0; i < 32; i += 8)
        out[(size_t)(c0 + ly + i) * R + r0 + lx] = t[lx][ly + i];
}

// ---------------- main GEMM ----------------
// At: [K, M] transposed weights. Bm: [K, N]. C: [M, N].
// CTA tile: BM=128 x BN=64. Thread tile: 8 rows x 4 cols (row-paired accs).
template <int MODE>
__global__ __launch_bounds__(256, 3)
void gemm_kernel(const float* __restrict__ At, const float* __restrict__ Bm,
                 float* __restrict__ C, int M, int N, int K)
{
    __shared__ float As[3][BK][BM];
    __shared__ float Bs[3][BK][BN];

    const int tid = threadIdx.x;
    const int m0 = blockIdx.y * BM;
    const int n0 = blockIdx.x * BN;
    const int tx = tid & 15;       // col group: 4 cols
    const int ty = tid >> 4;       // row group: 8 rows

    // loader coords
    const int al_row = tid >> 5;            // 0..7 (+8)
    const int al_col = (tid & 31) * 4;      // 16B chunk in 128-float row
    const int bl_row = tid >> 4;            // 0..15
    const int bl_col = (tid & 15) * 4;      // 16B chunk in 64-float row

    // acc2[pair p][col j] = (C[2p][j], C[2p+1][j]) for rows ty*8+2p(+1)
    u64 acc2[4][4];
    #pragma unroll
    for (int p = 0; p < 4; p++)
        #pragma unroll
        for (int j = 0; j < 4; j++) acc2[p][j] = 0ull;

    const int ntiles = K / BK;

    auto load_tile = [&](int s, int t) {
        const int kb = t * BK;
        #pragma unroll
        for (int it = 0; it < 2; it++) {
            const int r = al_row + it * 8;
            cp16((uint32_t)__cvta_generic_to_shared(&As[s][r][al_col]),
                 At + (size_t)(kb + r) * M + m0 + al_col);
        }
        cp16((uint32_t)__cvta_generic_to_shared(&Bs[s][bl_row][bl_col]),
             Bm + (size_t)(kb + bl_row) * N + n0 + bl_col);
        cp_commit();
    };

    load_tile(0, 0);
    load_tile(1, 1);

    for (int t = 0; t < ntiles; t++) {
        cp_wait<1>();
        __syncthreads();   // also protects stage (t+2)%3 == (t-1)%3 overwrite

        if (t + 2 < ntiles) load_tile((t + 2) % 3, t + 2);
        else cp_commit();

        const int cur = t % 3;

        #pragma unroll
        for (int k = 0; k < BK; k++) {
            // A: native row-pairs (adjacent m rows adjacent in smem)
            const ulonglong2 a01 = *(const ulonglong2*)&As[cur][k][ty * 8];
            const ulonglong2 a23 = *(const ulonglong2*)&As[cur][k][ty * 8 + 4];
            const u64 ap[4] = { a01.x, a01.y, a23.x, a23.y };
            // B: 4 scalars, broadcast-packed (4 MOVs)
            const float4 bv = *(const float4*)&Bs[cur][k][tx * 4];
            const u64 bb[4] = { pack2(bv.x, bv.x), pack2(bv.y, bv.y),
                                pack2(bv.z, bv.z), pack2(bv.w, bv.w) };

            #pragma unroll
            for (int p = 0; p < 4; p++)
                #pragma unroll
                for (int j = 0; j < 4; j++)
                    acc2[p][j] = fma2(ap[p], bb[j], acc2[p][j]);
        }
    }

    // ---- epilogue ----
    const int col = n0 + tx * 4;
    #pragma unroll
    for (int p = 0; p < 4; p++) {
        #pragma unroll
        for (int h = 0; h < 2; h++) {
            const int row = m0 + ty * 8 + 2 * p + h;
            float y[4];
            #pragma unroll
            for (int j = 0; j < 4; j++) {
                float lo, hi;
                unpack2(acc2[p][j], lo, hi);
                y[j] = h ? hi : lo;
            }
            if (MODE == MODE_HID) {
                float4 r = *(const float4*)(Bm + (size_t)row * N + col);
                y[0] += r.x; y[1] += r.y; y[2] += r.z; y[3] += r.w;
            }
            float4 o;
            #pragma unroll
            for (int q = 0; q < 4; q++) {
                float v = fminf(fmaxf(y[q], 0.0f), 1.0f);
                if (MODE != MODE_OUT) v = 2.0f * v - 1.0f;
                ((float*)&o)[q] = v;
            }
            *(float4*)(C + (size_t)row * N + col) = o;
        }
    }
}

extern "C" void kernel_launch(void* const* d_in, const int* in_sizes, int n_in,
                              void* d_out, int out_size)
{
    const float* x           = (const float*)d_in[0]; // [DIN, BATCH]
    const float* expansion   = (const float*)d_in[1]; // [HDIM, DIN]
    const float* hidden      = (const float*)d_in[2]; // [NLAYERS, HDIM, HDIM]
    const float* compression = (const float*)d_in[3]; // [DOUT, HDIM]
    float* out = (float*)d_out;                        // [DOUT, BATCH]

    float *act0, *xm, *wt, *et, *ct;
    cudaGetSymbolAddress((void**)&act0, g_act);
    cudaGetSymbolAddress((void**)&xm, g_xm);
    cudaGetSymbolAddress((void**)&wt, g_wt);
    cudaGetSymbolAddress((void**)&et, g_et);
    cudaGetSymbolAddress((void**)&ct, g_ct);
    float* act1 = act0 + (size_t)HDIM * BATCH;

    // ---- pre-pass: affine input + transpose all weight matrices ----
    affine_kernel<<<(DIN * BATCH / 4) / 256, 256>>>(x, xm);
    transpose_kernel<<<dim3(DIN / 32, HDIM / 32, 1), dim3(32, 8)>>>(expansion, et, HDIM, DIN);
    transpose_kernel<<<dim3(HDIM / 32, HDIM / 32, NLAYERS), dim3(32, 8)>>>(hidden, wt, HDIM, HDIM);
    transpose_kernel<<<dim3(HDIM / 32, DOUT / 32, 1), dim3(32, 8)>>>(compression, ct, DOUT, HDIM);

    dim3 blk(256);

    // Expansion: m0 = 2*clip(E @ (2x-1)) - 1
    gemm_kernel<MODE_EXP><<<dim3(BATCH / BN, HDIM / BM), blk>>>(
        et, xm, act0, HDIM, BATCH, DIN);

    // 64 hidden layers: m' = 2*clip(W m + m) - 1
    float* cur = act0;
    float* nxt = act1;
    for (int l = 0; l < NLAYERS; l++) {
        gemm_kernel<MODE_HID><<<dim3(BATCH / BN, HDIM / BM), blk>>>(
            wt + (size_t)l * HDIM * HDIM, cur, nxt, HDIM, BATCH, HDIM);
        float* tmp = cur; cur = nxt; nxt = tmp;
    }

    // Compression: out = clip(Cmp @ m)
    gemm_kernel<MODE_OUT><<<dim3(BATCH / BN, DOUT / BM), blk>>>(
        ct, cur, out, DOUT, BATCH, HDIM);
}

// round 15
// speedup vs baseline: 1.7229x; 1.0643x over previous
#include <cuda_runtime.h>
#include <cstdint>

// Problem constants
#define HDIM   1024
#define DIN    256
#define DOUT   256
#define BATCH  8192
#define NLAYERS 64
#define BK     32
#define BM     128
#define BN     64

// Scratch (device globals; allocation-free):
__device__ float g_act[2][HDIM * BATCH];                     // activations, m-form, [H, B]
__device__ float g_xm[DIN * BATCH];                          // 2x-1, [DIN, B]
__device__ float g_wt[(size_t)NLAYERS * HDIM * HDIM];        // W transposed: [l][k][m]
__device__ float g_et[(size_t)DIN * HDIM];                   // E transposed: [k][m]
__device__ float g_ct[(size_t)HDIM * DOUT];                  // C transposed: [k][m]

enum { MODE_EXP = 0, MODE_HID = 1, MODE_OUT = 2 };

typedef unsigned long long u64;

__device__ __forceinline__ u64 pack2(float lo, float hi) {
    u64 r;
    asm("mov.b64 %0, {%1, %2};" : "=l"(r) : "f"(lo), "f"(hi));
    return r;
}
__device__ __forceinline__ void unpack2(u64 v, float& lo, float& hi) {
    asm("mov.b64 {%0, %1}, %2;" : "=f"(lo), "=f"(hi) : "l"(v));
}
__device__ __forceinline__ u64 fma2(u64 a, u64 b, u64 c) {
    u64 d;
    asm("fma.rn.f32x2 %0, %1, %2, %3;" : "=l"(d) : "l"(a), "l"(b), "l"(c));
    return d;
}
__device__ __forceinline__ void cp16(uint32_t dst, const float* src) {
    asm volatile("cp.async.cg.shared.global [%0], [%1], 16;" :: "r"(dst), "l"(src));
}
__device__ __forceinline__ void cp_commit() {
    asm volatile("cp.async.commit_group;");
}
template <int N>
__device__ __forceinline__ void cp_wait() {
    asm volatile("cp.async.wait_group %0;" :: "n"(N));
}

// ---------------- pre-pass kernels ----------------
__global__ void affine_kernel(const float* __restrict__ x, float* __restrict__ xm) {
    int i = blockIdx.x * blockDim.x + threadIdx.x;
    float4 v = ((const float4*)x)[i];
    v.x = 2.0f * v.x - 1.0f; v.y = 2.0f * v.y - 1.0f;
    v.z = 2.0f * v.z - 1.0f; v.w = 2.0f * v.w - 1.0f;
    ((float4*)xm)[i] = v;
}

__global__ void transpose_kernel(const float* __restrict__ in, float* __restrict__ out,
                                 int R, int Cc) {
    __shared__ float t[32][33];
    const size_t off = (size_t)blockIdx.z * R * Cc;
    in += off; out += off;
    int c0 = blockIdx.x * 32, r0 = blockIdx.y * 32;
    int lx = threadIdx.x, ly = threadIdx.y;
    #pragma unroll
    for (int i = 0; i < 32; i += 8)
        t[ly + i][lx] = in[(size_t)(r0 + ly + i) * Cc + c0 + lx];
    __syncthreads();
    #pragma unroll
    for (int i = 0; i < 32; i += 8)
        out[(size_t)(c0 + ly + i) * R + r0 + lx] = t[lx][ly + i];
}

// ---------------- main GEMM ----------------
// At: [K, M] transposed weights. Bm: [K, N]. C: [M, N].
// CTA tile: BM=128 x BN=64, BK=32. Thread tile: 8 rows x 4 cols (row-paired accs).
#define A_STG (BK * BM)     // floats per A stage
#define B_STG (BK * BN)
#define SMEM_BYTES (3 * (A_STG + B_STG) * 4)

template <int MODE>
__global__ __launch_bounds__(256, 3)
void gemm_kernel(const float* __restrict__ At, const float* __restrict__ Bm,
                 float* __restrict__ C, int M, int N, int K)
{
    extern __shared__ float smem[];
    // layout: A stages at [0,3), B stages at [3*A_STG + s*B_STG)
    const int tid = threadIdx.x;
    const int m0 = blockIdx.y * BM;
    const int n0 = blockIdx.x * BN;
    const int tx = tid & 15;       // col group: 4 cols
    const int ty = tid >> 4;       // row group: 8 rows

    // loader coords
    const int al_row = tid >> 5;            // 0..7 (+8,+16,+24)
    const int al_col = (tid & 31) * 4;      // 16B chunk in 128-float row
    const int bl_row = tid >> 4;            // 0..15 (+16)
    const int bl_col = (tid & 15) * 4;      // 16B chunk in 64-float row

    u64 acc2[4][4];
    #pragma unroll
    for (int p = 0; p < 4; p++)
        #pragma unroll
        for (int j = 0; j < 4; j++) acc2[p][j] = 0ull;

    const int ntiles = K / BK;

    auto load_tile = [&](int s, int t) {
        const int kb = t * BK;
        float* As = smem + s * A_STG;
        float* Bs = smem + 3 * A_STG + s * B_STG;
        #pragma unroll
        for (int it = 0; it < 4; it++) {
            const int r = al_row + it * 8;
            cp16((uint32_t)__cvta_generic_to_shared(As + r * BM + al_col),
                 At + (size_t)(kb + r) * M + m0 + al_col);
        }
        #pragma unroll
        for (int it = 0; it < 2; it++) {
            const int r = bl_row + it * 16;
            cp16((uint32_t)__cvta_generic_to_shared(Bs + r * BN + bl_col),
                 Bm + (size_t)(kb + r) * N + n0 + bl_col);
        }
        cp_commit();
    };

    load_tile(0, 0);
    load_tile(1, 1);

    for (int t = 0; t < ntiles; t++) {
        cp_wait<1>();
        __syncthreads();   // also protects stage (t+2)%3 == (t-1)%3 overwrite

        if (t + 2 < ntiles) load_tile((t + 2) % 3, t + 2);
        else cp_commit();

        const float* As = smem + (t % 3) * A_STG;
        const float* Bs = smem + 3 * A_STG + (t % 3) * B_STG;

        #pragma unroll
        for (int k = 0; k < BK; k++) {
            const ulonglong2 a01 = *(const ulonglong2*)&As[k * BM + ty * 8];
            const ulonglong2 a23 = *(const ulonglong2*)&As[k * BM + ty * 8 + 4];
            const u64 ap[4] = { a01.x, a01.y, a23.x, a23.y };
            const float4 bv = *(const float4*)&Bs[k * BN + tx * 4];
            const u64 bb[4] = { pack2(bv.x, bv.x), pack2(bv.y, bv.y),
                                pack2(bv.z, bv.z), pack2(bv.w, bv.w) };

            #pragma unroll
            for (int p = 0; p < 4; p++)
                #pragma unroll
                for (int j = 0; j < 4; j++)
                    acc2[p][j] = fma2(ap[p], bb[j], acc2[p][j]);
        }
    }

    // ---- epilogue ----
    const int col = n0 + tx * 4;
    #pragma unroll
    for (int p = 0; p < 4; p++) {
        #pragma unroll
        for (int h = 0; h < 2; h++) {
            const int row = m0 + ty * 8 + 2 * p + h;
            float y[4];
            #pragma unroll
            for (int j = 0; j < 4; j++) {
                float lo, hi;
                unpack2(acc2[p][j], lo, hi);
                y[j] = h ? hi : lo;
            }
            if (MODE == MODE_HID) {
                float4 r = *(const float4*)(Bm + (size_t)row * N + col);
                y[0] += r.x; y[1] += r.y; y[2] += r.z; y[3] += r.w;
            }
            float4 o;
            #pragma unroll
            for (int q = 0; q < 4; q++) {
                float v = fminf(fmaxf(y[q], 0.0f), 1.0f);
                if (MODE != MODE_OUT) v = 2.0f * v - 1.0f;
                ((float*)&o)[q] = v;
            }
            *(float4*)(C + (size_t)row * N + col) = o;
        }
    }
}

extern "C" void kernel_launch(void* const* d_in, const int* in_sizes, int n_in,
                              void* d_out, int out_size)
{
    const float* x           = (const float*)d_in[0]; // [DIN, BATCH]
    const float* expansion   = (const float*)d_in[1]; // [HDIM, DIN]
    const float* hidden      = (const float*)d_in[2]; // [NLAYERS, HDIM, HDIM]
    const float* compression = (const float*)d_in[3]; // [DOUT, HDIM]
    float* out = (float*)d_out;                        // [DOUT, BATCH]

    float *act0, *xm, *wt, *et, *ct;
    cudaGetSymbolAddress((void**)&act0, g_act);
    cudaGetSymbolAddress((void**)&xm, g_xm);
    cudaGetSymbolAddress((void**)&wt, g_wt);
    cudaGetSymbolAddress((void**)&et, g_et);
    cudaGetSymbolAddress((void**)&ct, g_ct);
    float* act1 = act0 + (size_t)HDIM * BATCH;

    cudaFuncSetAttribute(gemm_kernel<MODE_EXP>, cudaFuncAttributeMaxDynamicSharedMemorySize, SMEM_BYTES);
    cudaFuncSetAttribute(gemm_kernel<MODE_HID>, cudaFuncAttributeMaxDynamicSharedMemorySize, SMEM_BYTES);
    cudaFuncSetAttribute(gemm_kernel<MODE_OUT>, cudaFuncAttributeMaxDynamicSharedMemorySize, SMEM_BYTES);

    // ---- pre-pass: affine input + transpose all weight matrices ----
    affine_kernel<<<(DIN * BATCH / 4) / 256, 256>>>(x, xm);
    transpose_kernel<<<dim3(DIN / 32, HDIM / 32, 1), dim3(32, 8)>>>(expansion, et, HDIM, DIN);
    transpose_kernel<<<dim3(HDIM / 32, HDIM / 32, NLAYERS), dim3(32, 8)>>>(hidden, wt, HDIM, HDIM);
    transpose_kernel<<<dim3(HDIM / 32, DOUT / 32, 1), dim3(32, 8)>>>(compression, ct, DOUT, HDIM);

    dim3 blk(256);

    // Expansion: m0 = 2*clip(E @ (2x-1)) - 1
    gemm_kernel<MODE_EXP><<<dim3(BATCH / BN, HDIM / BM), blk, SMEM_BYTES>>>(
        et, xm, act0, HDIM, BATCH, DIN);

    // 64 hidden layers: m' = 2*clip(W m + m) - 1
    float* cur = act0;
    float* nxt = act1;
    for (int l = 0; l < NLAYERS; l++) {
        gemm_kernel<MODE_HID><<<dim3(BATCH / BN, HDIM / BM), blk, SMEM_BYTES>>>(
            wt + (size_t)l * HDIM * HDIM, cur, nxt, HDIM, BATCH, HDIM);
        float* tmp = cur; cur = nxt; nxt = tmp;
    }

    // Compression: out = clip(Cmp @ m)
    gemm_kernel<MODE_OUT><<<dim3(BATCH / BN, DOUT / BM), blk, SMEM_BYTES>>>(
        ct, cur, out, DOUT, BATCH, HDIM);
}